// round 3
// baseline (speedup 1.0000x reference)
#include <cuda_runtime.h>

#define RR 4
#define ND 81
#define HH 128
#define WW 256
#define CC 128
#define BB 8

#define HT 8                 // tile height
#define WT 32                // tile width
#define CB 4                 // channels per stage
#define NCHUNK (CC/CB)       // 32
#define NSTG 4               // pipeline stages
#define WROWS (HT + 2*RR)    // 16 warped rows per channel
#define WROW 44              // warped row stride (floats); conflict-free (44%32==12)
#define XROW 36              // x row stride (floats)
#define WCH (WROWS*WROW)     // 704
#define XCH (HT*XROW)        // 288
#define CHSZ (WCH + XCH)     // 992 floats / channel
#define STG (CB*CHSZ)        // 3968 floats / stage
#define SMEM_BYTES (NSTG * STG * 4)   // 63488
#define NTHR 288             // 9 di * 8 h * 4 wgroups

typedef unsigned long long u64t;

static __device__ __forceinline__ u64t pk2(float lo, float hi) {
    return __double_as_longlong(__hiloint2double(__float_as_int(hi), __float_as_int(lo)));
}
static __device__ __forceinline__ void fma2(u64t &acc, u64t a, u64t b) {
    asm("fma.rn.f32x2 %0, %1, %2, %0;" : "+l"(acc) : "l"(a), "l"(b));
}
static __device__ __forceinline__ float lo32(u64t v) {
    return __int_as_float(__double2loint(__longlong_as_double(v)));
}
static __device__ __forceinline__ float hi32(u64t v) {
    return __int_as_float(__double2hiint(__longlong_as_double(v)));
}
static __device__ __forceinline__ void cpa16(unsigned dst, const float* src) {
    asm volatile("cp.async.cg.shared.global [%0], [%1], 16;" :: "r"(dst), "l"(src));
}
static __device__ __forceinline__ void cpa4(unsigned dst, const float* src) {
    asm volatile("cp.async.ca.shared.global [%0], [%1], 4;" :: "r"(dst), "l"(src));
}

extern __shared__ __align__(16) float smf[];

__global__ void __launch_bounds__(NTHR, 2)
cost_volume_kernel(const float* __restrict__ gx, const float* __restrict__ gw,
                   float* __restrict__ gout)
{
    const int tid = threadIdx.x;
    const int w0  = blockIdx.x * WT;
    const int h0  = blockIdx.y * HT;
    const int b   = blockIdx.z;

    const float* xb = gx + (size_t)b * CC * HH * WW;
    const float* wb = gw + (size_t)b * CC * HH * WW;
    const unsigned smb = (unsigned)__cvta_generic_to_shared(smf);

    // stage CB channels (warped halo tile + x tile) into buffer s; always commits
    auto do_stage = [&](int chunk, int s) {
        if (chunk < NCHUNK) {
            #pragma unroll
            for (int cc2 = 0; cc2 < CB; cc2++) {
                const int c = chunk * CB + cc2;
                const float* wc = wb + (size_t)c * HH * WW;
                const float* xc = xb + (size_t)c * HH * WW;
                float* smw = smf + s * STG + cc2 * CHSZ;
                const unsigned sbase = smb + (unsigned)((s * STG + cc2 * CHSZ) * 4);

                if (tid < 128) {                       // warped interior 16x32
                    const int row = tid >> 3, c4 = tid & 7;
                    const int gh  = h0 - RR + row;
                    const int off = row * WROW + RR + c4 * 4;
                    if ((unsigned)gh < HH)
                        cpa16(sbase + (unsigned)(off * 4), wc + gh * WW + w0 + c4 * 4);
                    else
                        *(float4*)(smw + off) = make_float4(0.f, 0.f, 0.f, 0.f);
                }
                if (tid >= 128 && tid < 192) {         // x tile 8x32
                    const int i = tid - 128;
                    const int row = i >> 3, c4 = i & 7;
                    cpa16(sbase + (unsigned)((WCH + row * XROW + c4 * 4) * 4),
                          xc + (h0 + row) * WW + w0 + c4 * 4);
                }
                if (tid >= 160) {                      // warped halo edges 16x(4+4)
                    const int e = tid - 160;
                    const int row = e >> 3, k = e & 7;
                    const int gh   = h0 - RR + row;
                    const int gcol = (k < 4) ? (w0 - RR + k) : (w0 + WT + k - 4);
                    const int soff = (k < 4) ? k : (32 + k);
                    if ((unsigned)gh < HH && (unsigned)gcol < WW)
                        cpa4(sbase + (unsigned)((row * WROW + soff) * 4), wc + gh * WW + gcol);
                    else
                        smw[row * WROW + soff] = 0.0f;
                }
            }
        }
        asm volatile("cp.async.commit_group;" ::: "memory");
    };

    const int dig = tid % 9;        // di + 4 (fastest: x broadcast across 9 lanes)
    const int hwg = tid / 9;
    const int h_i = hwg & 7;
    const int wg  = hwg >> 3;       // 0..3

    const int woff = (h_i + dig) * WROW + wg * 8;   // 16B aligned
    const int xoff = WCH + h_i * XROW + wg * 8;     // 16B aligned

    u64t acc[36];                   // [dj(9)][pixel-pair(4)]
    #pragma unroll
    for (int i = 0; i < 36; i++) acc[i] = 0ULL;

    do_stage(0, 0);
    do_stage(1, 1);
    do_stage(2, 2);

    for (int chunk = 0; chunk < NCHUNK; chunk++) {
        asm volatile("cp.async.wait_group 2;" ::: "memory");
        __syncthreads();

        const float* sb = smf + (chunk & (NSTG - 1)) * STG;

        #pragma unroll
        for (int cc2 = 0; cc2 < CB; cc2++) {
            const float* base = sb + cc2 * CHSZ;
            const ulonglong2* wv = (const ulonglong2*)(base + woff);
            const ulonglong2* xp = (const ulonglong2*)(base + xoff);

            // 8 even-aligned warped pairs, pre-packed by LDS.128
            ulonglong2 t0 = wv[0], t1 = wv[1], t2 = wv[2], t3 = wv[3];
            u64t we[8] = { t0.x, t0.y, t1.x, t1.y, t2.x, t2.y, t3.x, t3.y };
            ulonglong2 xt0 = xp[0], xt1 = xp[1];
            u64t xv[4] = { xt0.x, xt0.y, xt1.x, xt1.y };

            // walk window offsets o = dj + 2p in 0..14; build each pair once
            #pragma unroll
            for (int o = 0; o < 15; o++) {
                const u64t pair = (o & 1)
                    ? pk2(hi32(we[o >> 1]), lo32(we[(o >> 1) + 1]))
                    : we[o >> 1];
                #pragma unroll
                for (int p = 0; p < 4; p++) {
                    const int dj = o - 2 * p;
                    if (dj >= 0 && dj < 9)
                        fma2(acc[dj * 4 + p], xv[p], pair);
                }
            }
        }

        do_stage(chunk + 3, (chunk + 3) & (NSTG - 1));
    }

    // epilogue: scale by 1/(C*81), write 9 dj planes x 8 pixels
    const float sc = 1.0f / (float)(CC * ND);
    float* ob = gout + (((size_t)b * ND + dig * 9) * HH + (h0 + h_i)) * WW + w0 + wg * 8;
    #pragma unroll
    for (int dj = 0; dj < 9; dj++) {
        float* od = ob + (size_t)dj * HH * WW;
        #pragma unroll
        for (int p = 0; p < 4; p++) {
            u64t v = acc[dj * 4 + p];
            float2 r;
            r.x = lo32(v) * sc;
            r.y = hi32(v) * sc;
            *(float2*)(od + 2 * p) = r;
        }
    }
}

extern "C" void kernel_launch(void* const* d_in, const int* in_sizes, int n_in,
                              void* d_out, int out_size) {
    const float* x = (const float*)d_in[0];
    const float* w = (const float*)d_in[1];
    float* out = (float*)d_out;
    cudaFuncSetAttribute(cost_volume_kernel,
                         cudaFuncAttributeMaxDynamicSharedMemorySize, SMEM_BYTES);
    dim3 grid(WW / WT, HH / HT, BB);   // (8, 16, 8) = 1024 blocks
    cost_volume_kernel<<<grid, NTHR, SMEM_BYTES>>>(x, w, out);
}

// round 4
// speedup vs baseline: 1.2698x; 1.2698x over previous
#include <cuda_runtime.h>

#define RR 4
#define ND 81
#define HH 128
#define WW 256
#define CC 128
#define BB 8
#define HW (HH*WW)

#define HT 8                 // tile height
#define WT 32                // tile width
#define CB 4                 // channels per stage
#define NCHUNK (CC/CB)       // 32
#define NSTG 4               // pipeline stages (ring)
#define WROWS (HT + 2*RR)    // 16 warped rows per channel
#define WROW 44              // warped row stride (floats); 40 used; conflict-free
#define XROW 36              // x row stride (floats); 32 used
#define WCH (WROWS*WROW)     // 704
#define XCH (HT*XROW)        // 288
#define CHSZ (WCH + XCH)     // 992 floats / channel
#define STG (CB*CHSZ)        // 3968 floats / stage
#define SMEM_BYTES (NSTG * STG * 4)   // 63488
#define NTHR 288             // 9 di * 8 h * 4 wgroups

typedef unsigned long long u64t;

static __device__ __forceinline__ u64t pk2(float lo, float hi) {
    return __double_as_longlong(__hiloint2double(__float_as_int(hi), __float_as_int(lo)));
}
static __device__ __forceinline__ void fma2(u64t &acc, u64t a, u64t b) {
    asm("fma.rn.f32x2 %0, %1, %2, %0;" : "+l"(acc) : "l"(a), "l"(b));
}
static __device__ __forceinline__ float lo32(u64t v) {
    return __int_as_float(__double2loint(__longlong_as_double(v)));
}
static __device__ __forceinline__ float hi32(u64t v) {
    return __int_as_float(__double2hiint(__longlong_as_double(v)));
}
static __device__ __forceinline__ void cpa16(unsigned dst, const float* src) {
    asm volatile("cp.async.cg.shared.global [%0], [%1], 16;" :: "r"(dst), "l"(src));
}

extern __shared__ __align__(16) float smf[];

__global__ void __launch_bounds__(NTHR, 2)
cost_volume_kernel(const float* __restrict__ gx, const float* __restrict__ gw,
                   float* __restrict__ gout)
{
    const int tid = threadIdx.x;
    const int w0  = blockIdx.x * WT;
    const int h0  = blockIdx.y * HT;
    const int b   = blockIdx.z;

    const float* xb = gx + (size_t)b * CC * HW;
    const float* wb = gw + (size_t)b * CC * HW;
    const unsigned smb = (unsigned)__cvta_generic_to_shared(smf);

    // ---------- staging role: ONE float4 per thread per channel, hoisted ----------
    // items 0..159 : warped halo tile, 16 rows x 10 quads (cols w0-4 .. w0+35)
    // items 160..223: x tile, 8 rows x 8 quads
    // items 224..287: idle
    const float* gsrc = nullptr;   // channel-0 source (advances by CB*HW per chunk)
    int smoff = 0;                 // float offset within a channel slot
    bool active = false;

    if (tid < 160) {
        const int row = tid / 10, q = tid % 10;
        const int gh   = h0 - RR + row;
        const int gcol = w0 - RR + q * 4;           // 16B-aligned, fully in or out
        smoff  = row * WROW + q * 4;
        const bool valid = ((unsigned)gh < HH) && (gcol >= 0) && (gcol + 4 <= WW);
        if (valid) { gsrc = wb + (size_t)gh * WW + gcol; active = true; }
        else {
            // OOB positions are channel-independent: zero once in all stages
            #pragma unroll
            for (int s = 0; s < NSTG; s++)
                #pragma unroll
                for (int cc2 = 0; cc2 < CB; cc2++)
                    *(float4*)(smf + s * STG + cc2 * CHSZ + smoff) =
                        make_float4(0.f, 0.f, 0.f, 0.f);
        }
    } else if (tid < 224) {
        const int i = tid - 160;
        const int row = i / 8, q = i % 8;
        smoff = WCH + row * XROW + q * 4;
        gsrc  = xb + (size_t)(h0 + row) * WW + w0 + q * 4;
        active = true;
    }

    // per-stage smem destinations (bytes), hoisted
    unsigned sdst[NSTG];
    #pragma unroll
    for (int s = 0; s < NSTG; s++) sdst[s] = smb + (unsigned)((s * STG + smoff) * 4);

    const float* srcp = gsrc;      // running channel pointer
    // stage chunk'CB channels into ring slot s (compile-time s at call sites)
    auto do_stage = [&](int chunk, int s) {
        if (chunk < NCHUNK) {
            if (active) {
                #pragma unroll
                for (int cc2 = 0; cc2 < CB; cc2++)
                    cpa16(sdst[s] + (unsigned)(cc2 * CHSZ * 4), srcp + cc2 * HW);
                srcp += CB * HW;
            }
        }
        asm volatile("cp.async.commit_group;" ::: "memory");
    };

    // ---------- compute role ----------
    const int dig = tid % 9;        // di + 4 (x broadcast across the 9 lanes)
    const int hwg = tid / 9;
    const int h_i = hwg & 7;
    const int wg  = hwg >> 3;       // 0..3

    const int woff = (h_i + dig) * WROW + wg * 8;   // 16B aligned
    const int xoff = WCH + h_i * XROW + wg * 8;     // 16B aligned

    u64t acc[36];                   // [dj(9)][pixel-pair(4)]
    #pragma unroll
    for (int i = 0; i < 36; i++) acc[i] = 0ULL;

    do_stage(0, 0);
    do_stage(1, 1);
    do_stage(2, 2);

    // per-iteration body; STAGE is compile-time via the x4 unrolled loop
    auto body = [&](int chunk, int stage) {
        asm volatile("cp.async.wait_group 2;" ::: "memory");
        __syncthreads();

        const float* sb = smf + stage * STG;
        #pragma unroll
        for (int cc2 = 0; cc2 < CB; cc2++) {
            const float* base = sb + cc2 * CHSZ;
            const float4* wv4 = (const float4*)(base + woff);
            const float4* xv4 = (const float4*)(base + xoff);

            float wr[16];
            #pragma unroll
            for (int k = 0; k < 4; k++) {
                float4 t = wv4[k];
                wr[4*k+0] = t.x; wr[4*k+1] = t.y; wr[4*k+2] = t.z; wr[4*k+3] = t.w;
            }
            float4 x0 = xv4[0], x1 = xv4[1];
            u64t xv[4];
            xv[0] = pk2(x0.x, x0.y); xv[1] = pk2(x0.z, x0.w);
            xv[2] = pk2(x1.x, x1.y); xv[3] = pk2(x1.z, x1.w);

            #pragma unroll
            for (int p = 0; p < 4; p++) {
                #pragma unroll
                for (int dj = 0; dj < 9; dj++) {
                    fma2(acc[dj * 4 + p], xv[p], pk2(wr[2*p + dj], wr[2*p + dj + 1]));
                }
            }
        }

        do_stage(chunk + 3, (chunk + 3) & (NSTG - 1));
    };

    #pragma unroll 1
    for (int c = 0; c < NCHUNK; c += 4) {
        body(c + 0, 0);
        body(c + 1, 1);
        body(c + 2, 2);
        body(c + 3, 3);
    }

    // ---------- epilogue: scale by 1/(C*81), write 9 dj planes x 8 pixels ----------
    const float sc = 1.0f / (float)(CC * ND);
    float* ob = gout + (((size_t)b * ND + dig * 9) * HH + (h0 + h_i)) * WW + w0 + wg * 8;
    #pragma unroll
    for (int dj = 0; dj < 9; dj++) {
        float* od = ob + (size_t)dj * HW;
        #pragma unroll
        for (int p = 0; p < 4; p++) {
            u64t v = acc[dj * 4 + p];
            float2 r;
            r.x = lo32(v) * sc;
            r.y = hi32(v) * sc;
            *(float2*)(od + 2 * p) = r;
        }
    }
}

extern "C" void kernel_launch(void* const* d_in, const int* in_sizes, int n_in,
                              void* d_out, int out_size) {
    const float* x = (const float*)d_in[0];
    const float* w = (const float*)d_in[1];
    float* out = (float*)d_out;
    cudaFuncSetAttribute(cost_volume_kernel,
                         cudaFuncAttributeMaxDynamicSharedMemorySize, SMEM_BYTES);
    dim3 grid(WW / WT, HH / HT, BB);   // (8, 16, 8) = 1024 blocks
    cost_volume_kernel<<<grid, NTHR, SMEM_BYTES>>>(x, w, out);
}

// round 5
// speedup vs baseline: 1.4034x; 1.1053x over previous
#include <cuda_runtime.h>

#define RR 4
#define ND 81
#define HH 128
#define WW 256
#define CC 128
#define BB 8
#define HW (HH*WW)

#define HT 8                 // tile height
#define WT 16                // tile width
#define PW 4                 // pixels per thread (w)
#define CB 4                 // channels per stage
#define NCHUNK (CC/CB)       // 32
#define NSTG 4               // pipeline ring
#define WROWS (HT + 2*RR)    // 16 warped rows per channel
#define WROW 28              // warped row stride (floats); 24 used; starts mod 128B distinct
#define XROW 20              // x row stride (floats); 16 used
#define WCH (WROWS*WROW)     // 448
#define XCH (HT*XROW)        // 160
#define CHSZ (WCH + XCH)     // 608 floats / channel
#define STG (CB*CHSZ)        // 2432 floats / stage
#define SMEM_BYTES (NSTG * STG * 4)   // 38912
#define NTHR 288             // 9 di * 8 h * 4 wgroups

typedef unsigned long long u64t;

static __device__ __forceinline__ u64t pk2(float lo, float hi) {
    return __double_as_longlong(__hiloint2double(__float_as_int(hi), __float_as_int(lo)));
}
static __device__ __forceinline__ void fma2(u64t &acc, u64t a, u64t b) {
    asm("fma.rn.f32x2 %0, %1, %2, %0;" : "+l"(acc) : "l"(a), "l"(b));
}
static __device__ __forceinline__ float lo32(u64t v) {
    return __int_as_float(__double2loint(__longlong_as_double(v)));
}
static __device__ __forceinline__ float hi32(u64t v) {
    return __int_as_float(__double2hiint(__longlong_as_double(v)));
}
static __device__ __forceinline__ void cpa16(unsigned dst, const float* src) {
    asm volatile("cp.async.cg.shared.global [%0], [%1], 16;" :: "r"(dst), "l"(src));
}

extern __shared__ __align__(16) float smf[];

__global__ void __launch_bounds__(NTHR, 3)
cost_volume_kernel(const float* __restrict__ gx, const float* __restrict__ gw,
                   float* __restrict__ gout)
{
    const int tid = threadIdx.x;
    const int w0  = blockIdx.x * WT;
    const int h0  = blockIdx.y * HT;
    const int b   = blockIdx.z;

    const float* xb = gx + (size_t)b * CC * HW;
    const float* wb = gw + (size_t)b * CC * HW;
    const unsigned smb = (unsigned)__cvta_generic_to_shared(smf);

    // ---------- staging role: ONE float4 per thread per channel, fully hoisted ----------
    // tid 0..95  : warped halo tile, 16 rows x 6 quads (cols w0-4 .. w0+19)
    // tid 96..127: x tile, 8 rows x 4 quads
    // tid 128+   : idle for staging
    const float* gsrc = nullptr;
    int smoff = 0;
    bool active = false;

    if (tid < 96) {
        const int row = tid / 6, q = tid % 6;
        const int gh   = h0 - RR + row;
        const int gcol = w0 - RR + q * 4;           // quads fully in-range or fully OOB
        smoff = row * WROW + q * 4;
        const bool valid = ((unsigned)gh < HH) && (gcol >= 0) && (gcol + 4 <= WW);
        if (valid) { gsrc = wb + (size_t)gh * WW + gcol; active = true; }
        else {
            // OOB slots are channel-independent: zero once in every ring stage
            #pragma unroll
            for (int s = 0; s < NSTG; s++)
                #pragma unroll
                for (int cc2 = 0; cc2 < CB; cc2++)
                    *(float4*)(smf + s * STG + cc2 * CHSZ + smoff) =
                        make_float4(0.f, 0.f, 0.f, 0.f);
        }
    } else if (tid < 128) {
        const int i = tid - 96;
        const int row = i / 4, q = i % 4;
        smoff = WCH + row * XROW + q * 4;
        gsrc  = xb + (size_t)(h0 + row) * WW + w0 + q * 4;
        active = true;
    }

    unsigned sdst[NSTG];
    #pragma unroll
    for (int s = 0; s < NSTG; s++) sdst[s] = smb + (unsigned)((s * STG + smoff) * 4);

    const float* srcp = gsrc;
    auto do_stage = [&](int chunk, int s) {
        if (chunk < NCHUNK) {
            if (active) {
                #pragma unroll
                for (int cc2 = 0; cc2 < CB; cc2++)
                    cpa16(sdst[s] + (unsigned)(cc2 * CHSZ * 4), srcp + cc2 * HW);
                srcp += CB * HW;
            }
        }
        asm volatile("cp.async.commit_group;" ::: "memory");
    };

    // ---------- compute role ----------
    const int dig = tid % 9;        // di + 4 (x is an LDS broadcast across these 9 lanes)
    const int hwg = tid / 9;
    const int h_i = hwg & 7;
    const int wg  = hwg >> 3;       // 0..3

    const int woff = (h_i + dig) * WROW + wg * PW;  // 16B aligned
    const int xoff = WCH + h_i * XROW + wg * PW;    // 16B aligned

    u64t acc[18];                   // [dj(9)][pixel-pair(2)]
    #pragma unroll
    for (int i = 0; i < 18; i++) acc[i] = 0ULL;

    do_stage(0, 0);
    do_stage(1, 1);
    do_stage(2, 2);

    auto body = [&](int chunk, int stage) {
        asm volatile("cp.async.wait_group 2;" ::: "memory");
        __syncthreads();

        const float* sb = smf + stage * STG;
        #pragma unroll
        for (int cc2 = 0; cc2 < CB; cc2++) {
            const float* base = sb + cc2 * CHSZ;
            const float4* wv4 = (const float4*)(base + woff);
            const float4* xv4 = (const float4*)(base + xoff);

            float wr[12];
            #pragma unroll
            for (int k = 0; k < 3; k++) {
                float4 t = wv4[k];
                wr[4*k+0] = t.x; wr[4*k+1] = t.y; wr[4*k+2] = t.z; wr[4*k+3] = t.w;
            }
            float4 x0 = xv4[0];
            u64t xv[2];
            xv[0] = pk2(x0.x, x0.y);
            xv[1] = pk2(x0.z, x0.w);

            #pragma unroll
            for (int p = 0; p < 2; p++) {
                #pragma unroll
                for (int dj = 0; dj < 9; dj++) {
                    fma2(acc[dj * 2 + p], xv[p], pk2(wr[2*p + dj], wr[2*p + dj + 1]));
                }
            }
        }

        do_stage(chunk + 3, (chunk + 3) & (NSTG - 1));
    };

    #pragma unroll 1
    for (int c = 0; c < NCHUNK; c += 4) {
        body(c + 0, 0);
        body(c + 1, 1);
        body(c + 2, 2);
        body(c + 3, 3);
    }

    // ---------- epilogue: scale by 1/(C*81), write 9 dj planes x 4 pixels ----------
    const float sc = 1.0f / (float)(CC * ND);
    float* ob = gout + (((size_t)b * ND + dig * 9) * HH + (h0 + h_i)) * WW + w0 + wg * PW;
    #pragma unroll
    for (int dj = 0; dj < 9; dj++) {
        float* od = ob + (size_t)dj * HW;
        #pragma unroll
        for (int p = 0; p < 2; p++) {
            u64t v = acc[dj * 2 + p];
            float2 r;
            r.x = lo32(v) * sc;
            r.y = hi32(v) * sc;
            *(float2*)(od + 2 * p) = r;
        }
    }
}

extern "C" void kernel_launch(void* const* d_in, const int* in_sizes, int n_in,
                              void* d_out, int out_size) {
    const float* x = (const float*)d_in[0];
    const float* w = (const float*)d_in[1];
    float* out = (float*)d_out;
    cudaFuncSetAttribute(cost_volume_kernel,
                         cudaFuncAttributeMaxDynamicSharedMemorySize, SMEM_BYTES);
    dim3 grid(WW / WT, HH / HT, BB);   // (16, 16, 8) = 2048 blocks
    cost_volume_kernel<<<grid, NTHR, SMEM_BYTES>>>(x, w, out);
}